// round 16
// baseline (speedup 1.0000x reference)
#include <cuda_runtime.h>

#define BB 4
#define CC 256
#define HH 256
#define WW 256
#define HWSZ (HH * WW)
#define NPIX (BB * HWSZ)
#define FULLMASK 0xFFFFFFFFu

#define NBLK 592
#define NTHR 256
#define NTH_TOT (NBLK * NTHR)          // 151552 threads
#define NWARP (NBLK * 8)               // 4736 warps
// phase-2 tasks: 5 wbands x 3 hbands(90 rows) x 4 batches x 256 channels
#define NTASK (5 * 3 * 4 * 256)        // 15360 warp-tasks
#define HROWS 90                       // 18 ring-groups of 5
#define PROWS 274                      // rows 0,1 + 2..257 data + 258..273 zero
#define PPITCH 128                     // float2 per plane row
#define PLSZ (PROWS * PPITCH)
#define ZROW 258                       // first guaranteed-zero bottom pad row

typedef unsigned long long ull;
// packed f32x2 ops (sm_103a FFMA2 path; ptxas won't emit these from C++)
__device__ __forceinline__ ull fmul2(ull a, ull b) {
    ull r; asm("mul.rn.f32x2 %0, %1, %2;" : "=l"(r) : "l"(a), "l"(b)); return r;
}
__device__ __forceinline__ ull fadd2(ull a, ull b) {
    ull r; asm("add.rn.f32x2 %0, %1, %2;" : "=l"(r) : "l"(a), "l"(b)); return r;
}
__device__ __forceinline__ ull ffma2(ull a, ull b, ull c) {
    ull r; asm("fma.rn.f32x2 %0, %1, %2, %3;" : "=l"(r) : "l"(a), "l"(b), "l"(c)); return r;
}
#define NEG1X2 0xBF800000BF800000ULL   // (-1.0f, -1.0f)

// intermediates
__device__ unsigned char g_info[NPIX];
// fv plane: image row h stored at plane row h+2; fv = +-1 if correct (sign=class) else 0
__device__ float2 g_fvp[BB * PLSZ];
// iv plane: image row h stored at plane row h+2; iv = +-1/(cnt+1e-5) if mse-masked else 0
__device__ float2 g_ivp[BB * PLSZ];
__device__ double g_loss[2];
__device__ int g_nsel[2], g_cal[2];
__device__ int g_task;
__device__ int g_bar_count = 0;
__device__ volatile int g_bar_gen = 0;

__device__ __forceinline__ void gridsync() {
    __syncthreads();
    if (threadIdx.x == 0) {
        __threadfence();
        int gen = g_bar_gen;
        if (atomicAdd(&g_bar_count, 1) == NBLK - 1) {
            g_bar_count = 0;
            __threadfence();
            g_bar_gen = gen + 1;
        } else {
            while (g_bar_gen == gen) { __nanosleep(64); }
        }
        __threadfence();
    }
    __syncthreads();
}

__global__ void __launch_bounds__(NTHR, 4) kernFused(
    const float* __restrict__ x, const float* __restrict__ clf,
    const int* __restrict__ gt, float* __restrict__ out) {
    __shared__ double sred[2][8];
    const int tid0 = blockIdx.x * NTHR + threadIdx.x;

    // ================= Phase 1a: per-pixel info + plane pad zeroing =========
    for (int i = tid0; i < BB * 18 * WW; i += NTH_TOT) {
        int col = i & 255;
        int j = (i >> 8) % 18;
        int b = (i >> 8) / 18;
        int row = (j < 2) ? j : (j + 256);      // rows 0,1,258..273
        ((float*)(g_fvp + (size_t)b * PLSZ))[row * WW + col] = 0.f;
        ((float*)(g_ivp + (size_t)b * PLSZ))[row * WW + col] = 0.f;
    }
    for (int p = tid0; p < NPIX; p += NTH_TOT) {
        if (p == 0) {
            g_loss[0] = 0.0; g_loss[1] = 0.0;
            g_nsel[0] = 0; g_nsel[1] = 0;
            g_cal[0] = 0; g_cal[1] = 0;
            g_task = 0;
        }
        int b = p >> 16;
        int hw = p & (HWSZ - 1);
        int h = hw >> 8;
        int w = hw & (WW - 1);
        int g = gt[p];
        float c0 = clf[(size_t)(b * 2) * HWSZ + hw];
        float c1 = clf[(size_t)(b * 2 + 1) * HWSZ + hw];
        int pred = (c1 > c0) ? 1 : 0;          // argmax ties -> index 0
        int correct = (pred == g) ? 1 : 0;
        int edge = (g == -1) ? 1 : 0;
        if (h < HH - 5) edge |= (gt[p + 5 * WW] != g) ? 1 : 0;
        if (w < WW - 5) edge |= (gt[p + 5] != g) ? 1 : 0;
        g_info[p] = (unsigned char)((g & 1) | (correct << 1) | (edge << 2));
    }
    gridsync();

    // ================= Phase 1b: ring counts -> fv/iv planes + counters =====
    for (int p = tid0; p < NPIX; p += NTH_TOT) {
        int b = p >> 16;
        int hw = p & (HWSZ - 1);
        int h = hw >> 8;
        int w = hw & (WW - 1);
        unsigned info = g_info[p];
        int g = info & 1;
        int correct = (info >> 1) & 1;
        int edge = (info >> 2) & 1;
        int cntCorr = 0, cntCls = 0;
#pragma unroll
        for (int dh = -2; dh <= 2; dh++) {
#pragma unroll
            for (int dw = -2; dw <= 2; dw++) {
                if (dh == 0 && dw == 0) continue;
                int hh = h + dh, wp = w + dw;
                if ((unsigned)hh < HH && (unsigned)wp < WW) {
                    unsigned qi = g_info[p + dh * WW + dw];
                    int same = ((int)(qi & 1) == g) ? 1 : 0;
                    cntCls += same;
                    cntCorr += same & (int)((qi >> 1) & 1);
                }
            }
        }
        int mse = correct & edge & (cntCorr >= 1 ? 1 : 0);
        int cal = edge & (cntCls >= 1 ? 1 : 0);

        float fv = correct ? (g ? 1.0f : -1.0f) : 0.0f;
        float inv = 1.0f / ((float)cntCorr + 1e-5f);
        float ivs = mse ? (g ? inv : -inv) : 0.0f;

        ((float*)(g_fvp + (size_t)b * PLSZ))[(h + 2) * WW + w] = fv;
        ((float*)(g_ivp + (size_t)b * PLSZ))[(h + 2) * WW + w] = ivs;

        unsigned bm;
        bm = __ballot_sync(FULLMASK, mse && g == 0);
        if ((threadIdx.x & 31) == 0 && bm) atomicAdd(&g_nsel[0], __popc(bm));
        bm = __ballot_sync(FULLMASK, mse && g == 1);
        if ((threadIdx.x & 31) == 0 && bm) atomicAdd(&g_nsel[1], __popc(bm));
        bm = __ballot_sync(FULLMASK, cal && g == 0);
        if ((threadIdx.x & 31) == 0 && bm) atomicAdd(&g_cal[0], __popc(bm));
        bm = __ballot_sync(FULLMASK, cal && g == 1);
        if ((threadIdx.x & 31) == 0 && bm) atomicAdd(&g_cal[1], __popc(bm));
    }
    gridsync();

    // ================= Phase 2: separable 2-class box filter ================
    // Champion geometry (span-2, 5 wbands, parked pointers, ring-5, packed
    // f32x2 math, work stealing) with 90-row hbands: prologue overhead drops
    // 13.3% -> 4.4%. Rows 256..269 of the last hband are dead by construction
    // (iv plane rows there are zero; x clamped; fv plane rows <= 273 all zero).
    const int lane = threadIdx.x & 31;
    const int wid = threadIdx.x >> 5;
    float acc0 = 0.f, acc1 = 0.f;

    for (;;) {
        int t;
        if (lane == 0) t = atomicAdd(&g_task, 1);
        t = __shfl_sync(FULLMASK, t, 0);
        if (t >= NTASK) break;

        int wband = t % 5;
        int r1 = t / 5;
        int hband = r1 % 3;
        int r2 = r1 / 3;
        int b = r2 & 3;
        int ch = r2 >> 2;
        int h0 = hband * HROWS;
        int wl = wband * 60 - 2 + (lane << 1);
        bool colv = (wl >= 0) && (wl <= 254);
        bool qv = colv && (lane >= 1) && (lane <= 30);
        int wc = colv ? wl : (wl < 0 ? 0 : 254);
        int pc = wc >> 1;                       // float2 col in planes

        const float* xc = x + ((size_t)(b * CC + ch) << 16) + wc;
        const float2* plb = g_fvp + (size_t)b * PLSZ;
        const float2* ilb = g_ivp + (size_t)b * PLSZ;
        // main-loop plane pointers: park invalid lanes on a zero row, stride 0
        const float2* fvp = colv ? (plb + (h0 + 4) * PPITCH + pc) : (plb + ZROW * PPITCH);
        const float2* ivp = qv ? (ilb + (h0 + 2) * PPITCH + pc) : (ilb + ZROW * PPITCH);
        const int fstep = colv ? 5 * PPITCH : 0;
        const int istep = qv ? 5 * PPITCH : 0;

        ull pt[5], ps[5];                      // packed (x,y) products
        ull u = 0ULL, v = 0ULL;

        // prologue rows h0-2..h0+1 -> ring slots 0..3 (fv plane rows h0..h0+3)
        const float2* fvpro = colv ? (plb + h0 * PPITCH + pc) : (plb + ZROW * PPITCH);
#pragma unroll
        for (int k = 0; k < 4; k++) {
            int r = h0 - 2 + k;
            int rc = r < 0 ? 0 : r;
            float2 xvf = __ldg((const float2*)(xc + (rc << 8)));
            float2 fvf = __ldg(fvpro + k * PPITCH);
            ull X = *(ull*)&xvf;
            ull F = *(ull*)&fvf;
            ull S = fmul2(X, F);               // x*f
            ull T = fmul2(S, F);               // x*f^2 = x*|f|
            pt[k] = T; ps[k] = S;
            u = fadd2(u, T);
            v = fadd2(v, S);
        }
        pt[4] = 0ULL;
        ps[4] = 0ULL;

#pragma unroll 1
        for (int g = 0; g < HROWS / 5; g++) {
            const int rbase = h0 + 2 + g * 5;
            // batch-prefetch the 5 DRAM x rows (MLP 5)
            float2 xn[5];
#pragma unroll
            for (int k = 0; k < 5; k++) {
                int r = rbase + k;
                int rc = r > 255 ? 255 : r;
                xn[k] = __ldg((const float2*)(xc + (rc << 8)));
            }
#pragma unroll
            for (int k = 0; k < 5; k++) {
                const int sn = (k + 4) % 5;    // departing slot
                const int sc = (k + 2) % 5;    // center-row slot
                // L2-resident plane loads, immediate offsets
                float2 fvf = __ldg(fvp + k * PPITCH);
                float2 iv = __ldg(ivp + k * PPITCH);
                // slide out departing row (packed fma with -1)
                u = ffma2(pt[sn], NEG1X2, u);
                v = ffma2(ps[sn], NEG1X2, v);
                // slide in incoming row
                ull X = *(ull*)&xn[k];
                ull F = *(ull*)&fvf;
                ull S = fmul2(X, F);
                ull T = fmul2(S, F);
                pt[sn] = T; ps[sn] = S;
                u = fadd2(u, T);
                v = fadd2(v, S);
                // horizontal halo via shuffles
                float2 uf = *(float2*)&u;
                float2 vf = *(float2*)&v;
                float ulx = __shfl_up_sync(FULLMASK, uf.x, 1);
                float uly = __shfl_up_sync(FULLMASK, uf.y, 1);
                float urx = __shfl_down_sync(FULLMASK, uf.x, 1);
                float ury = __shfl_down_sync(FULLMASK, uf.y, 1);
                float vlx = __shfl_up_sync(FULLMASK, vf.x, 1);
                float vly = __shfl_up_sync(FULLMASK, vf.y, 1);
                float vrx = __shfl_down_sync(FULLMASK, vf.x, 1);
                float vry = __shfl_down_sync(FULLMASK, vf.y, 1);
                float cu = uly + uf.x + uf.y + urx;
                float cw = vly + vf.x + vf.y + vrx;
                float u50 = ulx + cu, u51 = cu + ury;
                float v50 = vlx + cw, v51 = cw + vry;
                // epilogue; class = sign(iv), zero iv -> no accumulation
                float s20 = iv.x, s21 = iv.y;
                float2 cen = *(float2*)&pt[sc];    // = x at masked px
                float a0 = fabsf(s20), a1 = fabsf(s21);
                float t10 = fmaf(0.5f, u50, -cen.x);
                float t11 = fmaf(0.5f, u51, -cen.y);
                float dd0 = fmaf(-0.5f * s20, v50, fmaf(-t10, a0, cen.x));
                float dd1 = fmaf(-0.5f * s21, v51, fmaf(-t11, a1, cen.y));
                float q0 = dd0 * dd0, q1 = dd1 * dd1;
                if (s20 > 0.f) acc1 += q0; else if (s20 < 0.f) acc0 += q0;
                if (s21 > 0.f) acc1 += q1; else if (s21 < 0.f) acc0 += q1;
            }
            fvp += fstep;
            ivp += istep;
        }
    }

    // block reduction -> 2 double atomics per block
#pragma unroll
    for (int o = 16; o; o >>= 1) {
        acc0 += __shfl_xor_sync(FULLMASK, acc0, o);
        acc1 += __shfl_xor_sync(FULLMASK, acc1, o);
    }
    if (lane == 0) { sred[0][wid] = (double)acc0; sred[1][wid] = (double)acc1; }
    __syncthreads();
    if (threadIdx.x == 0) {
        double t0 = 0.0, t1 = 0.0;
#pragma unroll
        for (int i = 0; i < 8; i++) { t0 += sred[0][i]; t1 += sred[1][i]; }
        atomicAdd(&g_loss[0], t0);
        atomicAdd(&g_loss[1], t1);
    }
    gridsync();

    // ================= Phase 3: finalize =====================================
    if (blockIdx.x == 0 && threadIdx.x == 0) {
        double total = 0.0;
        int ncls = 0;
#pragma unroll
        for (int c = 0; c < 2; c++) {
            int ns = *(volatile int*)&g_nsel[c];
            int ca = *(volatile int*)&g_cal[c];
            double ls = *(volatile double*)&g_loss[c];
            bool valid = (ca >= 1) && (ns >= 1);
            double denom = (double)ns * 256.0;
            if (denom < 1.0) denom = 1.0;
            if (valid) { total += ls / denom; ncls++; }
        }
        out[0] = (ncls == 0) ? 0.0f : (float)(total / (double)ncls);
    }
}

extern "C" void kernel_launch(void* const* d_in, const int* in_sizes, int n_in,
                              void* d_out, int out_size) {
    const float* xfeat = (const float*)d_in[0];   // [4,256,256,256] f32
    const float* clf   = (const float*)d_in[1];   // [4,2,256,256]   f32
    const int*   gt    = (const int*)d_in[2];     // [4,256,256]     i32
    float* out = (float*)d_out;

    kernFused<<<NBLK, NTHR>>>(xfeat, clf, gt, out);
}

// round 17
// speedup vs baseline: 1.1255x; 1.1255x over previous
#include <cuda_runtime.h>

#define BB 4
#define CC 256
#define HH 256
#define WW 256
#define HWSZ (HH * WW)
#define NPIX (BB * HWSZ)
#define FULLMASK 0xFFFFFFFFu

#define NBLK 592
#define NTHR 256
#define NTH_TOT (NBLK * NTHR)          // 151552 threads
#define NWARP (NBLK * 8)               // 4736 warps
#define NTASK (5 * 9 * 4 * 256)        // 46080 warp-tasks (30-row bands)
#define PROWS 274                      // rows 0,1 + 2..257 data + 258..273 zero
#define PPITCH 128                     // float2 per iv plane row
#define PLSZ (PROWS * PPITCH)
// fv byte plane: 256 bytes per row (no col halo needed; halos go via shuffles)
#define PBY 256
#define PLSZB (PROWS * PBY)            // 70144 bytes per batch
#define ZROW 258                       // first guaranteed-zero bottom pad row

typedef unsigned long long ull;
// packed f32x2 ops (sm_103a FFMA2 path; ptxas won't emit these from C++)
__device__ __forceinline__ ull fmul2(ull a, ull b) {
    ull r; asm("mul.rn.f32x2 %0, %1, %2;" : "=l"(r) : "l"(a), "l"(b)); return r;
}
__device__ __forceinline__ ull fadd2(ull a, ull b) {
    ull r; asm("add.rn.f32x2 %0, %1, %2;" : "=l"(r) : "l"(a), "l"(b)); return r;
}
__device__ __forceinline__ ull ffma2(ull a, ull b, ull c) {
    ull r; asm("fma.rn.f32x2 %0, %1, %2, %3;" : "=l"(r) : "l"(a), "l"(b), "l"(c)); return r;
}
#define NEG1X2 0xBF800000BF800000ULL   // (-1.0f, -1.0f)

// decode 2 signed bytes -> packed f32x2 in a ull
__device__ __forceinline__ ull decfv2(unsigned hv) {
    float2 r;
    r.x = (float)(int)(signed char)(hv & 0xFF);
    r.y = (float)(int)(signed char)((hv >> 8) & 0xFF);
    return *(ull*)&r;
}

// intermediates
__device__ unsigned char g_info[NPIX];
// fv byte plane: image row h at plane row h+2; fv = +-1 if correct (sign=class) else 0
__device__ uint4 g_fvb[BB * PLSZB / 16];
// iv plane: image row h stored at plane row h+2; iv = +-1/(cnt+1e-5) if mse-masked else 0
__device__ float2 g_ivp[BB * PLSZ];
__device__ double g_loss[2];
__device__ int g_nsel[2], g_cal[2];
__device__ int g_task;
__device__ int g_bar_count = 0;
__device__ volatile int g_bar_gen = 0;

__device__ __forceinline__ void gridsync() {
    __syncthreads();
    if (threadIdx.x == 0) {
        __threadfence();
        int gen = g_bar_gen;
        if (atomicAdd(&g_bar_count, 1) == NBLK - 1) {
            g_bar_count = 0;
            __threadfence();
            g_bar_gen = gen + 1;
        } else {
            while (g_bar_gen == gen) { __nanosleep(64); }
        }
        __threadfence();
    }
    __syncthreads();
}

__global__ void __launch_bounds__(NTHR, 4) kernFused(
    const float* __restrict__ x, const float* __restrict__ clf,
    const int* __restrict__ gt, float* __restrict__ out) {
    __shared__ double sred[2][8];
    const int tid0 = blockIdx.x * NTHR + threadIdx.x;

    // ================= Phase 1a: per-pixel info + plane pad zeroing =========
    // iv float plane pad rows (0,1,258..273) and fv byte plane pad rows.
    for (int i = tid0; i < BB * 18 * WW; i += NTH_TOT) {
        int col = i & 255;
        int j = (i >> 8) % 18;
        int b = (i >> 8) / 18;
        int row = (j < 2) ? j : (j + 256);      // rows 0,1,258..273
        ((float*)(g_ivp + (size_t)b * PLSZ))[row * WW + col] = 0.f;
        ((unsigned char*)g_fvb)[(size_t)b * PLSZB + row * PBY + col] = 0;
    }
    for (int p = tid0; p < NPIX; p += NTH_TOT) {
        if (p == 0) {
            g_loss[0] = 0.0; g_loss[1] = 0.0;
            g_nsel[0] = 0; g_nsel[1] = 0;
            g_cal[0] = 0; g_cal[1] = 0;
            g_task = 0;
        }
        int b = p >> 16;
        int hw = p & (HWSZ - 1);
        int h = hw >> 8;
        int w = hw & (WW - 1);
        int g = gt[p];
        float c0 = clf[(size_t)(b * 2) * HWSZ + hw];
        float c1 = clf[(size_t)(b * 2 + 1) * HWSZ + hw];
        int pred = (c1 > c0) ? 1 : 0;          // argmax ties -> index 0
        int correct = (pred == g) ? 1 : 0;
        int edge = (g == -1) ? 1 : 0;
        if (h < HH - 5) edge |= (gt[p + 5 * WW] != g) ? 1 : 0;
        if (w < WW - 5) edge |= (gt[p + 5] != g) ? 1 : 0;
        g_info[p] = (unsigned char)((g & 1) | (correct << 1) | (edge << 2));
    }
    gridsync();

    // ================= Phase 1b: ring counts -> fv/iv planes + counters =====
    for (int p = tid0; p < NPIX; p += NTH_TOT) {
        int b = p >> 16;
        int hw = p & (HWSZ - 1);
        int h = hw >> 8;
        int w = hw & (WW - 1);
        unsigned info = g_info[p];
        int g = info & 1;
        int correct = (info >> 1) & 1;
        int edge = (info >> 2) & 1;
        int cntCorr = 0, cntCls = 0;
#pragma unroll
        for (int dh = -2; dh <= 2; dh++) {
#pragma unroll
            for (int dw = -2; dw <= 2; dw++) {
                if (dh == 0 && dw == 0) continue;
                int hh = h + dh, wp = w + dw;
                if ((unsigned)hh < HH && (unsigned)wp < WW) {
                    unsigned qi = g_info[p + dh * WW + dw];
                    int same = ((int)(qi & 1) == g) ? 1 : 0;
                    cntCls += same;
                    cntCorr += same & (int)((qi >> 1) & 1);
                }
            }
        }
        int mse = correct & edge & (cntCorr >= 1 ? 1 : 0);
        int cal = edge & (cntCls >= 1 ? 1 : 0);

        signed char fvb = correct ? (g ? 1 : -1) : 0;
        float inv = 1.0f / ((float)cntCorr + 1e-5f);
        float ivs = mse ? (g ? inv : -inv) : 0.0f;

        ((signed char*)g_fvb)[(size_t)b * PLSZB + (h + 2) * PBY + w] = fvb;
        ((float*)(g_ivp + (size_t)b * PLSZ))[(h + 2) * WW + w] = ivs;

        unsigned bm;
        bm = __ballot_sync(FULLMASK, mse && g == 0);
        if ((threadIdx.x & 31) == 0 && bm) atomicAdd(&g_nsel[0], __popc(bm));
        bm = __ballot_sync(FULLMASK, mse && g == 1);
        if ((threadIdx.x & 31) == 0 && bm) atomicAdd(&g_nsel[1], __popc(bm));
        bm = __ballot_sync(FULLMASK, cal && g == 0);
        if ((threadIdx.x & 31) == 0 && bm) atomicAdd(&g_cal[0], __popc(bm));
        bm = __ballot_sync(FULLMASK, cal && g == 1);
        if ((threadIdx.x & 31) == 0 && bm) atomicAdd(&g_cal[1], __popc(bm));
    }
    gridsync();

    // ================= Phase 2: separable 2-class box filter ================
    // Champion geometry (span-2, 5 wbands x 9 hbands of 30 rows, parked
    // pointers, ring-5, packed f32x2, work stealing) + int8 fv plane (2-byte
    // lane loads, decoded to f32x2; halos still via shuffles of u,v).
    const int lane = threadIdx.x & 31;
    const int wid = threadIdx.x >> 5;
    float acc0 = 0.f, acc1 = 0.f;

    for (;;) {
        int t;
        if (lane == 0) t = atomicAdd(&g_task, 1);
        t = __shfl_sync(FULLMASK, t, 0);
        if (t >= NTASK) break;

        int wband = t % 5;
        int r1 = t / 5;
        int hband = r1 % 9;
        int r2 = r1 / 9;
        int b = r2 & 3;
        int ch = r2 >> 2;
        int h0 = hband * 30;
        int wl = wband * 60 - 2 + (lane << 1);
        bool colv = (wl >= 0) && (wl <= 254);
        bool qv = colv && (lane >= 1) && (lane <= 30);
        int wc = colv ? wl : (wl < 0 ? 0 : 254);
        int pc = wc >> 1;                       // float2 col in iv plane

        const float* xc = x + ((size_t)(b * CC + ch) << 16) + wc;
        const unsigned char* fbB = (const unsigned char*)g_fvb + (size_t)b * PLSZB;
        const float2* ilb = g_ivp + (size_t)b * PLSZ;
        // main-loop plane pointers: park invalid lanes on a zero row, stride 0
        const unsigned char* fvp = colv ? (fbB + (h0 + 4) * PBY + wc) : (fbB + ZROW * PBY);
        const float2* ivp = qv ? (ilb + (h0 + 2) * PPITCH + pc) : (ilb + ZROW * PPITCH);
        const int fstep = colv ? 5 * PBY : 0;
        const int istep = qv ? 5 * PPITCH : 0;

        ull pt[5], ps[5];                      // packed (x,y) products
        ull u = 0ULL, v = 0ULL;

        // prologue rows h0-2..h0+1 -> ring slots 0..3 (fv plane rows h0..h0+3)
        const unsigned char* fvpro = colv ? (fbB + h0 * PBY + wc) : (fbB + ZROW * PBY);
#pragma unroll
        for (int k = 0; k < 4; k++) {
            int r = h0 - 2 + k;
            int rc = r < 0 ? 0 : r;
            float2 xvf = __ldg((const float2*)(xc + (rc << 8)));
            unsigned hv = __ldg((const unsigned short*)(fvpro + k * PBY));
            ull X = *(ull*)&xvf;
            ull F = decfv2(hv);
            ull S = fmul2(X, F);               // x*f
            ull T = fmul2(S, F);               // x*f^2 = x*|f|
            pt[k] = T; ps[k] = S;
            u = fadd2(u, T);
            v = fadd2(v, S);
        }
        pt[4] = 0ULL;
        ps[4] = 0ULL;

#pragma unroll 1
        for (int g = 0; g < 6; g++) {
            const int rbase = h0 + 2 + g * 5;
            // batch-prefetch the 5 DRAM x rows (MLP 5)
            float2 xn[5];
#pragma unroll
            for (int k = 0; k < 5; k++) {
                int r = rbase + k;
                int rc = r > 255 ? 255 : r;
                xn[k] = __ldg((const float2*)(xc + (rc << 8)));
            }
#pragma unroll
            for (int k = 0; k < 5; k++) {
                const int sn = (k + 4) % 5;    // departing slot
                const int sc = (k + 2) % 5;    // center-row slot
                // L2/L1-resident plane loads, immediate offsets
                unsigned hv = __ldg((const unsigned short*)(fvp + k * PBY));
                float2 iv = __ldg(ivp + k * PPITCH);
                // slide out departing row (packed fma with -1)
                u = ffma2(pt[sn], NEG1X2, u);
                v = ffma2(ps[sn], NEG1X2, v);
                // slide in incoming row
                ull X = *(ull*)&xn[k];
                ull F = decfv2(hv);
                ull S = fmul2(X, F);
                ull T = fmul2(S, F);
                pt[sn] = T; ps[sn] = S;
                u = fadd2(u, T);
                v = fadd2(v, S);
                // horizontal halo via shuffles
                float2 uf = *(float2*)&u;
                float2 vf = *(float2*)&v;
                float ulx = __shfl_up_sync(FULLMASK, uf.x, 1);
                float uly = __shfl_up_sync(FULLMASK, uf.y, 1);
                float urx = __shfl_down_sync(FULLMASK, uf.x, 1);
                float ury = __shfl_down_sync(FULLMASK, uf.y, 1);
                float vlx = __shfl_up_sync(FULLMASK, vf.x, 1);
                float vly = __shfl_up_sync(FULLMASK, vf.y, 1);
                float vrx = __shfl_down_sync(FULLMASK, vf.x, 1);
                float vry = __shfl_down_sync(FULLMASK, vf.y, 1);
                float cu = uly + uf.x + uf.y + urx;
                float cw = vly + vf.x + vf.y + vrx;
                float u50 = ulx + cu, u51 = cu + ury;
                float v50 = vlx + cw, v51 = cw + vry;
                // epilogue; class = sign(iv), zero iv -> no accumulation
                float s20 = iv.x, s21 = iv.y;
                float2 cen = *(float2*)&pt[sc];    // = x at masked px
                float a0 = fabsf(s20), a1 = fabsf(s21);
                float t10 = fmaf(0.5f, u50, -cen.x);
                float t11 = fmaf(0.5f, u51, -cen.y);
                float dd0 = fmaf(-0.5f * s20, v50, fmaf(-t10, a0, cen.x));
                float dd1 = fmaf(-0.5f * s21, v51, fmaf(-t11, a1, cen.y));
                float q0 = dd0 * dd0, q1 = dd1 * dd1;
                if (s20 > 0.f) acc1 += q0; else if (s20 < 0.f) acc0 += q0;
                if (s21 > 0.f) acc1 += q1; else if (s21 < 0.f) acc0 += q1;
            }
            fvp += fstep;
            ivp += istep;
        }
    }

    // block reduction -> 2 double atomics per block
#pragma unroll
    for (int o = 16; o; o >>= 1) {
        acc0 += __shfl_xor_sync(FULLMASK, acc0, o);
        acc1 += __shfl_xor_sync(FULLMASK, acc1, o);
    }
    if (lane == 0) { sred[0][wid] = (double)acc0; sred[1][wid] = (double)acc1; }
    __syncthreads();
    if (threadIdx.x == 0) {
        double t0 = 0.0, t1 = 0.0;
#pragma unroll
        for (int i = 0; i < 8; i++) { t0 += sred[0][i]; t1 += sred[1][i]; }
        atomicAdd(&g_loss[0], t0);
        atomicAdd(&g_loss[1], t1);
    }
    gridsync();

    // ================= Phase 3: finalize =====================================
    if (blockIdx.x == 0 && threadIdx.x == 0) {
        double total = 0.0;
        int ncls = 0;
#pragma unroll
        for (int c = 0; c < 2; c++) {
            int ns = *(volatile int*)&g_nsel[c];
            int ca = *(volatile int*)&g_cal[c];
            double ls = *(volatile double*)&g_loss[c];
            bool valid = (ca >= 1) && (ns >= 1);
            double denom = (double)ns * 256.0;
            if (denom < 1.0) denom = 1.0;
            if (valid) { total += ls / denom; ncls++; }
        }
        out[0] = (ncls == 0) ? 0.0f : (float)(total / (double)ncls);
    }
}

extern "C" void kernel_launch(void* const* d_in, const int* in_sizes, int n_in,
                              void* d_out, int out_size) {
    const float* xfeat = (const float*)d_in[0];   // [4,256,256,256] f32
    const float* clf   = (const float*)d_in[1];   // [4,2,256,256]   f32
    const int*   gt    = (const int*)d_in[2];     // [4,256,256]     i32
    float* out = (float*)d_out;

    kernFused<<<NBLK, NTHR>>>(xfeat, clf, gt, out);
}